// round 6
// baseline (speedup 1.0000x reference)
#include <cuda_runtime.h>
#include <cuda_fp16.h>
#include <cstdint>

#define N_OBS 2048
#define KH    1024
#define DIN   64
#define NTILE 8          // KH / 128
#define NPAIR 36         // upper-triangle tile pairs
#define NSPLIT 4         // split-K factor for kernelB

// Scratch (device globals: allocation-free per harness rules)
__device__ __half g_sT[KH * N_OBS];                  // 4 MB: sin activations fp16, (k, n)
__device__ float  g_M[KH * KH];                      // 4 MB: full symmetric Gram
__device__ float  g_Mp[NSPLIT * NPAIR * 128 * 128];  // 9.4 MB: per-(split,tile) partials

// ---------------------------------------------------------------------------
// Helpers
// ---------------------------------------------------------------------------
__device__ __forceinline__ void pair_from_idx(int idx, int& tr, int& tc) {
    int t = 0, rem = idx;
    while (rem >= NTILE - t) { rem -= NTILE - t; t++; }
    tr = t; tc = t + rem;
}
__device__ __forceinline__ uint32_t smem_u32(const void* p) {
    uint32_t a;
    asm("{ .reg .u64 t; cvta.to.shared.u64 t, %1; cvt.u32.u64 %0, t; }" : "=r"(a) : "l"(p));
    return a;
}
__device__ __forceinline__ void cp_async16(uint32_t dst, const void* src) {
    asm volatile("cp.async.cg.shared.global [%0], [%1], 16;" :: "r"(dst), "l"(src));
}
#define CP_COMMIT() asm volatile("cp.async.commit_group;" ::: "memory")
#define CP_WAIT1()  asm volatile("cp.async.wait_group 1;" ::: "memory")
#define CP_WAIT0()  asm volatile("cp.async.wait_group 0;" ::: "memory")

__device__ __forceinline__ void ldmatrix_x4(uint32_t* r, uint32_t addr) {
    asm volatile("ldmatrix.sync.aligned.m8n8.x4.shared.b16 {%0,%1,%2,%3}, [%4];"
                 : "=r"(r[0]), "=r"(r[1]), "=r"(r[2]), "=r"(r[3]) : "r"(addr));
}
// mma m16n8k16 fp16 in, fp32 accumulate
__device__ __forceinline__ void mma_f16(float* c, const uint32_t* a, const uint32_t* b) {
    asm volatile(
        "mma.sync.aligned.m16n8k16.row.col.f32.f16.f16.f32 "
        "{%0,%1,%2,%3}, {%4,%5,%6,%7}, {%8,%9}, {%0,%1,%2,%3};"
        : "+f"(c[0]), "+f"(c[1]), "+f"(c[2]), "+f"(c[3])
        : "r"(a[0]), "r"(a[1]), "r"(a[2]), "r"(a[3]), "r"(b[0]), "r"(b[1]));
}
// Blackwell packed dual-FMA: per-half acc += a * b  (b64 registers)
__device__ __forceinline__ void ffma2(unsigned long long& acc,
                                      unsigned long long a, unsigned long long b) {
    asm("fma.rn.f32x2 %0, %1, %2, %0;" : "+l"(acc) : "l"(a), "l"(b));
}

// ---------------------------------------------------------------------------
// Kernel A: g_sT[k][n] = half( __sinf( dot(x[n,:], w[k,:]) + b[k] ) )
// grid = (KH/32, N_OBS/128), 256 threads. Warp: 4 k-rows x 128 n.
// Hot loop uses packed f32x2 FMA (half the fma-pipe ops of scalar FFMA).
// ---------------------------------------------------------------------------
#define A_KT 32
#define A_NC 128
#define A_XPAD 132

__global__ void __launch_bounds__(256) kernelA(const float* __restrict__ x,
                                               const float* __restrict__ w,
                                               const float* __restrict__ b) {
    __shared__ float  xsT[DIN][A_XPAD];     // 33.8 KB  xsT[d][n_local]
    __shared__ float2 wks2[A_KT][DIN];      // 16 KB    duplicated (w,w) pairs

    const int tid = threadIdx.x;
    const int k0  = blockIdx.x * A_KT;
    const int n0  = blockIdx.y * A_NC;

    for (int i = tid; i < A_NC * DIN; i += 256) {
        const int n = i >> 6, d = i & 63;
        xsT[d][n] = x[(size_t)(n0 + n) * DIN + d];      // coalesced read
    }
    for (int i = tid; i < A_KT * DIN; i += 256) {
        const int k = i >> 6, d = i & 63;
        const float v = w[(size_t)(k0 + k) * DIN + d];
        wks2[k][d] = make_float2(v, v);
    }
    __syncthreads();

    const int warp  = tid >> 5;
    const int lane4 = (tid & 31) * 4;
    const int r0 = warp * 4;

    unsigned long long acc01[4], acc23[4];
    #pragma unroll
    for (int r = 0; r < 4; r++) { acc01[r] = 0ull; acc23[r] = 0ull; }

    #pragma unroll 8
    for (int d = 0; d < DIN; d++) {
        const ulonglong2 xv = *(const ulonglong2*)&xsT[d][lane4];   // LDS.128, pairs free
        #pragma unroll
        for (int r = 0; r < 4; r++) {
            const unsigned long long wv2 =
                *(const unsigned long long*)&wks2[r0 + r][d];       // LDS.64 broadcast
            ffma2(acc01[r], xv.x, wv2);
            ffma2(acc23[r], xv.y, wv2);
        }
    }

    #pragma unroll
    for (int r = 0; r < 4; r++) {
        const float bv = b[k0 + r0 + r];
        const float a0 = __uint_as_float((uint32_t)acc01[r]);
        const float a1 = __uint_as_float((uint32_t)(acc01[r] >> 32));
        const float a2 = __uint_as_float((uint32_t)acc23[r]);
        const float a3 = __uint_as_float((uint32_t)(acc23[r] >> 32));
        __half2 p0 = __floats2half2_rn(__sinf(a0 + bv), __sinf(a1 + bv));
        __half2 p1 = __floats2half2_rn(__sinf(a2 + bv), __sinf(a3 + bv));
        uint2 u;
        u.x = *(uint32_t*)&p0;
        u.y = *(uint32_t*)&p1;
        *(uint2*)&g_sT[(size_t)(k0 + r0 + r) * N_OBS + n0 + lane4] = u;   // 8B store
    }
}

// ---------------------------------------------------------------------------
// Kernel B: partial Gram via fp16 mma.m16n8k16 + ldmatrix, cp.async dbl-buffer.
// grid = (36 pairs, 4 splits), 256 threads (8 warps 4x2, warp tile 32x64).
// Chunk = 32 n (64B/row). Row stride 80B -> conflict-free ldmatrix.
// ---------------------------------------------------------------------------
#define B_ROWB  80                    // 64B data + 16B pad
#define B_OPB   (128 * B_ROWB)        // 10240 B per operand tile
#define B_BUF   (2 * B_OPB)           // one (A,B) buffer pair
#define B_SMEMB (2 * B_BUF)           // 40960 B double-buffered
#define B_NCH   16                    // 512 n per CTA / 32 per chunk

__global__ void __launch_bounds__(256) kernelB_f16() {
    __shared__ __align__(16) char sm[B_SMEMB];

    const int tid = threadIdx.x;
    const int wid = tid >> 5;
    const int lid = tid & 31;
    const int g   = lid >> 2;
    const int t4  = lid & 3;

    int tr, tc; pair_from_idx(blockIdx.x, tr, tc);
    const int i0 = tr * 128, l0 = tc * 128;
    const bool diag = (tr == tc);
    const int ops  = diag ? 1 : 2;
    const int nb   = blockIdx.y * (N_OBS / NSPLIT);

    const uint32_t sb = smem_u32(sm);
    const int wr = wid & 3;            // i offset wr*32
    const int wc = wid >> 2;           // l offset wc*64
    const int ibase = wr * 32, lbase = wc * 64;

    float c[2][8][4];
    #pragma unroll
    for (int mi = 0; mi < 2; mi++)
        #pragma unroll
        for (int ni = 0; ni < 8; ni++)
            #pragma unroll
            for (int t = 0; t < 4; t++) c[mi][ni][t] = 0.f;

    auto stage = [&](int ch, int buf) {
        const int n0 = nb + ch * 32;
        const int tot = ops << 9;                        // 512 cp.async per operand
        for (int e = tid; e < tot; e += 256) {
            const int op  = e >> 9;
            const int idx = e & 511;
            const int row = idx >> 2;
            const int c16 = idx & 3;
            const int grow = (op ? l0 : i0) + row;
            cp_async16(sb + (uint32_t)(buf * B_BUF + op * B_OPB + row * B_ROWB + c16 * 16),
                       &g_sT[(size_t)grow * N_OBS + n0 + c16 * 8]);
        }
    };

    // per-lane ldmatrix address offsets (within an operand tile)
    const uint32_t aOff0 = (uint32_t)((ibase + (lid & 15)) * B_ROWB + (lid >> 4) * 16);
    const uint32_t bRow  = (uint32_t)(lbase + ((lid >> 4) << 3) + (lid & 7));
    const uint32_t bOff0 = bRow * B_ROWB + ((lid >> 3) & 1) * 16;

    stage(0, 0);
    CP_COMMIT();

    for (int ch = 0; ch < B_NCH; ch++) {
        const int buf = ch & 1;
        if (ch + 1 < B_NCH) { stage(ch + 1, buf ^ 1); CP_COMMIT(); CP_WAIT1(); }
        else                { CP_WAIT0(); }
        __syncthreads();

        const uint32_t aBase = sb + buf * B_BUF;
        const uint32_t bBase = diag ? aBase : aBase + B_OPB;

        #pragma unroll
        for (int ks = 0; ks < 2; ks++) {                 // two k16 steps per 32-n chunk
            uint32_t a[2][4];
            #pragma unroll
            for (int mi = 0; mi < 2; mi++)
                ldmatrix_x4(a[mi], aBase + aOff0 + (uint32_t)(mi * 16 * B_ROWB + ks * 32));
            uint32_t bb[4][4];
            #pragma unroll
            for (int p = 0; p < 4; p++)
                ldmatrix_x4(bb[p], bBase + bOff0 + (uint32_t)(p * 16 * B_ROWB + ks * 32));
            #pragma unroll
            for (int mi = 0; mi < 2; mi++)
                #pragma unroll
                for (int ni = 0; ni < 8; ni++)
                    mma_f16(c[mi][ni], a[mi], &bb[ni >> 1][(ni & 1) * 2]);
        }
        __syncthreads();                                 // reads done before buf reuse
    }

    // Epilogue: scale + store partial tile
    const float sc = (2.0f / (float)KH) / (float)N_OBS;
    float* dst = &g_Mp[((size_t)blockIdx.y * NPAIR + blockIdx.x) * (128 * 128)];
    #pragma unroll
    for (int mi = 0; mi < 2; mi++) {
        const int rr = ibase + 16 * mi + g;
        #pragma unroll
        for (int ni = 0; ni < 8; ni++) {
            const int cc = lbase + 8 * ni + 2 * t4;
            float2 v0 = make_float2(c[mi][ni][0] * sc, c[mi][ni][1] * sc);
            float2 v1 = make_float2(c[mi][ni][2] * sc, c[mi][ni][3] * sc);
            *(float2*)&dst[(size_t)rr * 128 + cc]       = v0;
            *(float2*)&dst[(size_t)(rr + 8) * 128 + cc] = v1;
        }
    }
}

// ---------------------------------------------------------------------------
// Kernel R: reduce 4 split-partials, write M tile + mirrored tile.
// grid = 36 tiles * 4 row-quarters, 256 threads.
// ---------------------------------------------------------------------------
__global__ void __launch_bounds__(256) kernelR() {
    __shared__ float ts[32][133];

    const int tid  = threadIdx.x;
    const int tile = blockIdx.x >> 2;
    const int q    = blockIdx.x & 3;
    int tr, tc; pair_from_idx(tile, tr, tc);
    const int i0 = tr * 128 + q * 32;
    const int l0 = tc * 128;

    for (int e = tid; e < 32 * 128; e += 256) {
        const int r = e >> 7, c = e & 127;
        float v = 0.f;
        #pragma unroll
        for (int s = 0; s < NSPLIT; s++)
            v += g_Mp[((size_t)s * NPAIR + tile) * (128 * 128) + (size_t)(q * 32 + r) * 128 + c];
        ts[r][c] = v;
    }
    __syncthreads();

    for (int e = tid; e < 32 * 128; e += 256) {
        const int r = e >> 7, c = e & 127;
        g_M[(size_t)(i0 + r) * KH + l0 + c] = ts[r][c];
    }
    if (tr != tc) {
        for (int e = tid; e < 128 * 32; e += 256) {
            const int lr = e >> 5, kc = e & 31;
            g_M[(size_t)(l0 + lr) * KH + i0 + kc] = ts[kc][lr];
        }
    }
}

// ---------------------------------------------------------------------------
// Kernel C: A[d,k,l] = M[k,l] * w[k,d] * w[l,d]  (256 MB store-bound)
// grid = (KH/128, KH/8), 256 threads, 8 CTAs/SM. At the HBM-write wall.
// ---------------------------------------------------------------------------
#define C_KT 8
#define C_LT 128
#define C_WPAD 132

__global__ void __launch_bounds__(256, 8) kernelC(const float* __restrict__ w,
                                                  float* __restrict__ out) {
    __shared__ float wld[32][C_WPAD];     // 16.9 KB (one d-half at a time)
    __shared__ float Ms[C_KT][C_LT];      // 4 KB
    __shared__ float wks[DIN][C_KT + 1];  // 2.3 KB

    const int tid = threadIdx.x;
    const int l0  = blockIdx.x * C_LT;
    const int k0  = blockIdx.y * C_KT;

    for (int i = tid; i < C_KT * C_LT; i += 256) {
        const int kk = i >> 7, li = i & 127;
        Ms[kk][li] = g_M[(size_t)(k0 + kk) * KH + l0 + li];
    }
    for (int i = tid; i < C_KT * DIN; i += 256) {
        const int kk = i >> 6, d = i & 63;
        wks[d][kk] = w[(size_t)(k0 + kk) * DIN + d];
    }

    const int j     = tid >> 5;
    const int lane4 = (tid & 31) * 4;

    float4 M4;
    const size_t base = (size_t)(k0 + j) * KH + l0 + lane4;

    #pragma unroll
    for (int h = 0; h < 2; h++) {
        __syncthreads();
        for (int i = tid; i < 32 * C_LT; i += 256) {
            const int li = i >> 5, d = i & 31;
            wld[d][li] = w[(size_t)(l0 + li) * DIN + h * 32 + d];   // coalesced
        }
        __syncthreads();
        if (h == 0) M4 = *(const float4*)&Ms[j][lane4];

        #pragma unroll 8
        for (int dd = 0; dd < 32; dd++) {
            const int d = h * 32 + dd;
            const float wk  = wks[d][j];
            const float4 wl = *(const float4*)&wld[dd][lane4];
            float4 o;
            o.x = (M4.x * wk) * wl.x;
            o.y = (M4.y * wk) * wl.y;
            o.z = (M4.z * wk) * wl.z;
            o.w = (M4.w * wk) * wl.w;
            __stcs((float4*)&out[(size_t)d * (size_t)(KH * KH) + base], o);
        }
    }
}

// ---------------------------------------------------------------------------
extern "C" void kernel_launch(void* const* d_in, const int* in_sizes, int n_in,
                              void* d_out, int out_size) {
    (void)in_sizes; (void)n_in; (void)out_size;
    const float* x = (const float*)d_in[0];
    const float* w = (const float*)d_in[1];
    const float* b = (const float*)d_in[2];
    float* out = (float*)d_out;

    kernelA<<<dim3(KH / A_KT, N_OBS / A_NC), 256>>>(x, w, b);
    kernelB_f16<<<dim3(NPAIR, NSPLIT), 256>>>();
    kernelR<<<NPAIR * 4, 256>>>();
    kernelC<<<dim3(KH / C_LT, KH / C_KT), 256>>>(w, out);
}